// round 12
// baseline (speedup 1.0000x reference)
#include <cuda_runtime.h>
#include <cstdint>

// Problem-fixed sizes (reference: N=100000, F_IN=512, F_OUT=2).
#define NMAX 100000
#define FOUT 2
#define FIN 512

#define DEG_BLOCKS 60
#define GEMM_BLOCKS 384
#define FUSED_BLOCKS (DEG_BLOCKS + GEMM_BLOCKS)  // 444 = 148 SMs * 3 CTAs

#define TILE_ROWS 16
#define ROW_BYTES (FIN * 4 + 16)                  // 2064 B: 16B pad -> LDS.128 conflict-free
#define TILE_BYTES (TILE_ROWS * ROW_BYTES)        // 33024 B
#define SMEM_W_OFF (2 * TILE_BYTES)               // W: 512x2 floats = 4096 B
#define SMEM_P_OFF (2 * TILE_BYTES + 4096)        // partials: 16 seg x 16 row x 2 = 2048 B
#define SMEM_TOTAL (2 * TILE_BYTES + 4096 + 2048) // 72192 B -> 3 CTAs/SM

// __device__ globals are zero-initialized at module load; every call restores
// them to zero before finishing (post re-zeros g_deg, head resets scalar +
// ticket), so each graph replay sees identical initial state.
__device__ __align__(16) float g_deg[NMAX];
__device__ __align__(16) float g_dis[NMAX];
__device__ __align__(16) float g_h[NMAX * FOUT];   // x @ W
__device__ __align__(16) float g_hs[NMAX * FOUT];  // h * dis (gather source)
__device__ __align__(16) float g_acc[NMAX * FOUT]; // self-loop + edge sums
__device__ float g_acc_scalar;
__device__ unsigned int g_ticket;

// ---------------------------------------------------------------------------
// Dummies align the fused kernel onto the profiler's capture slot (idx 3).
__global__ void dummy_kernel() {}

__device__ __forceinline__ void cp16(uint32_t dst_smem, const void* src) {
    asm volatile("cp.async.cg.shared.global [%0], [%1], 16;"
                 :: "r"(dst_smem), "l"(src) : "memory");
}

// ---------------------------------------------------------------------------
// K1 (fused, persistent): blocks [0, DEG_BLOCKS) = deg segment-sum atomics;
// blocks [DEG_BLOCKS, 444) = GEMM via cp.async double-buffered smem tiles.
// cp.async carries the x stream with no register cost -> ~3 CTAs x 32KB of
// loads in flight per SM (far beyond the latency-hiding requirement), while
// the smem compute path needs zero warp shuffles.
__global__ __launch_bounds__(256) void fused_gemm_deg(
        const float* __restrict__ x, const float* __restrict__ W, int n,
        const int* __restrict__ col, const float* __restrict__ w, int E) {
    if ((int)blockIdx.x < DEG_BLOCKS) {
        int t0 = (int)blockIdx.x * 256 + threadIdx.x;
        const int nthr = DEG_BLOCKS * 256;
        int nq = E >> 2;
        for (int q = t0; q < nq; q += nthr) {
            int4 c4 = *(const int4*)(col + q * 4);
            float4 w4 = *(const float4*)(w + q * 4);
            atomicAdd(&g_deg[c4.x], w4.x);
            atomicAdd(&g_deg[c4.y], w4.y);
            atomicAdd(&g_deg[c4.z], w4.z);
            atomicAdd(&g_deg[c4.w], w4.w);
        }
        if (t0 == 0) {
            for (int e = nq * 4; e < E; ++e) atomicAdd(&g_deg[col[e]], w[e]);
        }
        return;
    }
    // --- GEMM ---
    extern __shared__ char smem[];
    float4* Wsm4 = (float4*)(smem + SMEM_W_OFF);
    float* psum = (float*)(smem + SMEM_P_OFF);
    int tid = threadIdx.x;
    uint32_t sbase = (uint32_t)__cvta_generic_to_shared(smem);

    // Stage W into smem (visible after the first in-loop barrier).
    Wsm4[tid] = ((const float4*)W)[tid];  // FIN*FOUT/4 = 256 float4

    const int NT = n >> 4;                // 16-row tiles (n % 16 == 0)
    int g = (int)blockIdx.x - DEG_BLOCKS;
    if (g >= NT) return;

    const float4* x4 = (const float4*)x;

    // prologue: issue tile g into buffer 0
    {
        uint32_t dbase = sbase;
        int rowbase = g * TILE_ROWS;
#pragma unroll
        for (int i = 0; i < 8; i++) {
            int chunk = tid + 256 * i;          // 0..2047
            int row = chunk >> 7;               // 128 chunks (16B) per row
            int c16 = chunk & 127;
            cp16(dbase + row * ROW_BYTES + c16 * 16,
                 x4 + (size_t)(rowbase + row) * (FIN / 4) + c16);
        }
        asm volatile("cp.async.commit_group;" ::: "memory");
    }

    int p = 0;
    int seg = tid >> 4, r = tid & 15;
    for (;;) {
        int gn = g + GEMM_BLOCKS;
        bool hn = (gn < NT);
        if (hn) {
            uint32_t dbase = sbase + (1 - p) * TILE_BYTES;
            int rowbase = gn * TILE_ROWS;
#pragma unroll
            for (int i = 0; i < 8; i++) {
                int chunk = tid + 256 * i;
                int row = chunk >> 7;
                int c16 = chunk & 127;
                cp16(dbase + row * ROW_BYTES + c16 * 16,
                     x4 + (size_t)(rowbase + row) * (FIN / 4) + c16);
            }
            asm volatile("cp.async.commit_group;" ::: "memory");
            asm volatile("cp.async.wait_group 1;" ::: "memory");
        } else {
            asm volatile("cp.async.wait_group 0;" ::: "memory");
        }
        __syncthreads();   // tile g complete in all threads; W/psum ordered

        // stage 1: thread (seg, r) reduces k in [seg*32, seg*32+32) of row r
        {
            const float4* xrow = (const float4*)(smem + p * TILE_BYTES + r * ROW_BYTES);
            float a0 = 0.f, a1 = 0.f;
#pragma unroll
            for (int j = 0; j < 8; j++) {
                float4 v = xrow[seg * 8 + j];
                float4 w0 = Wsm4[seg * 16 + 2 * j];
                float4 w1 = Wsm4[seg * 16 + 2 * j + 1];
                a0 += v.x * w0.x + v.y * w0.z + v.z * w1.x + v.w * w1.z;
                a1 += v.x * w0.y + v.y * w0.w + v.z * w1.y + v.w * w1.w;
            }
            psum[seg * 32 + r * 2 + 0] = a0;
            psum[seg * 32 + r * 2 + 1] = a1;
        }
        __syncthreads();

        // stage 2: warp 0 sums the 16 segment partials per (row, out)
        if (tid < 32) {
            int rr = tid >> 1, j = tid & 1;
            float s = 0.f;
#pragma unroll
            for (int sg = 0; sg < 16; sg++) s += psum[sg * 32 + rr * 2 + j];
            g_h[(g * TILE_ROWS + rr) * 2 + j] = s;
        }
        if (!hn) break;
        g = gn;
        p ^= 1;
    }
}

// ---------------------------------------------------------------------------
// K2: dis = rsqrt(deg + 1); hs = h*dis; acc = hs (self-loop, weight 1);
// re-zero g_deg for the next replay.
__global__ void post_kernel(int n) {
    int i = blockIdx.x * blockDim.x + threadIdx.x;
    if (i >= n) return;
    float d = g_deg[i] + 1.0f;  // self-loop weight
    g_deg[i] = 0.0f;            // restore initial state for next call
    float dis = rsqrtf(d);      // d >= 1 always
    g_dis[i] = dis;
    float2 h = *(const float2*)(g_h + 2 * i);
    float2 hs = make_float2(h.x * dis, h.y * dis);
    *(float2*)(g_hs + 2 * i) = hs;
    *(float2*)(g_acc + 2 * i) = hs;
}

// ---------------------------------------------------------------------------
// K3: edge scatter: acc[col] += hs[row] * w. One random 8B gather + one v2
// RED per edge; 4 edges/thread for gather ILP. (~sector-floor bound in L2.)
__global__ __launch_bounds__(256) void edge_kernel(
        const int* __restrict__ row, const int* __restrict__ col,
        const float* __restrict__ w, int E) {
    int t = blockIdx.x * blockDim.x + threadIdx.x;
    int base = t * 4;
    if (base + 3 < E) {
        int4 r4 = *(const int4*)(row + base);
        int4 c4 = *(const int4*)(col + base);
        float4 w4 = *(const float4*)(w + base);
        float2 h0 = __ldg((const float2*)(g_hs + 2 * r4.x));
        float2 h1 = __ldg((const float2*)(g_hs + 2 * r4.y));
        float2 h2 = __ldg((const float2*)(g_hs + 2 * r4.z));
        float2 h3 = __ldg((const float2*)(g_hs + 2 * r4.w));
        asm volatile("red.global.add.v2.f32 [%0], {%1, %2};" ::
                     "l"(g_acc + 2 * c4.x), "f"(h0.x * w4.x), "f"(h0.y * w4.x) : "memory");
        asm volatile("red.global.add.v2.f32 [%0], {%1, %2};" ::
                     "l"(g_acc + 2 * c4.y), "f"(h1.x * w4.y), "f"(h1.y * w4.y) : "memory");
        asm volatile("red.global.add.v2.f32 [%0], {%1, %2};" ::
                     "l"(g_acc + 2 * c4.z), "f"(h2.x * w4.z), "f"(h2.y * w4.z) : "memory");
        asm volatile("red.global.add.v2.f32 [%0], {%1, %2};" ::
                     "l"(g_acc + 2 * c4.w), "f"(h3.x * w4.w), "f"(h3.y * w4.w) : "memory");
    } else {
        for (int e = base; e < E; ++e) {
            int r = row[e], c = col[e];
            float ww = w[e];
            float2 hv = __ldg((const float2*)(g_hs + 2 * r));
            asm volatile("red.global.add.v2.f32 [%0], {%1, %2};" ::
                         "l"(g_acc + 2 * c), "f"(hv.x * ww), "f"(hv.y * ww) : "memory");
        }
    }
}

// ---------------------------------------------------------------------------
// K4: head (+ fused final): relu(dis*acc + b) · fc_w -> g_acc_scalar; last
// block applies sigmoid into d_out and resets scalar state for next replay.
__global__ void head_kernel(const float* __restrict__ bvec,
                            const float* __restrict__ fcw,
                            const float* __restrict__ fcb,
                            float* __restrict__ out, int n, int nblocks) {
    int i = blockIdx.x * blockDim.x + threadIdx.x;
    float p = 0.f;
    if (i < n) {
        float dis = g_dis[i];
        float2 a = *(const float2*)(g_acc + 2 * i);
        float2 fw = *(const float2*)(fcw + 2 * i);
        float v0 = fmaxf(dis * a.x + bvec[0], 0.f);
        float v1 = fmaxf(dis * a.y + bvec[1], 0.f);
        p = v0 * fw.x + v1 * fw.y;
    }
#pragma unroll
    for (int off = 16; off; off >>= 1) p += __shfl_down_sync(0xffffffffu, p, off);
    __shared__ float ws[8];
    __shared__ bool is_last;
    int lane = threadIdx.x & 31, wid = threadIdx.x >> 5;
    if (lane == 0) ws[wid] = p;
    __syncthreads();
    if (wid == 0) {
        p = (lane < (blockDim.x >> 5)) ? ws[lane] : 0.f;
#pragma unroll
        for (int off = 4; off; off >>= 1) p += __shfl_down_sync(0xffffffffu, p, off);
        if (lane == 0) {
            atomicAdd(&g_acc_scalar, p);
            __threadfence();
            unsigned int t = atomicAdd(&g_ticket, 1u);
            is_last = (t == (unsigned int)(nblocks - 1));
        }
    }
    __syncthreads();
    if (is_last && threadIdx.x == 0) {
        float l = g_acc_scalar + fcb[0];
        out[0] = 1.f / (1.f + expf(-l));
        g_acc_scalar = 0.0f;   // restore initial state for next call
        g_ticket = 0u;
    }
}

// ---------------------------------------------------------------------------
extern "C" void kernel_launch(void* const* d_in, const int* in_sizes, int n_in,
                              void* d_out, int out_size) {
    const float* x   = (const float*)d_in[0];      // [N, F_IN]
    const int*   el  = (const int*)d_in[1];        // [2, E] int32 (JAX downcast)
    const float* ea  = (const float*)d_in[2];      // [E]
    const float* W   = (const float*)d_in[3];      // [F_IN, 2]
    const float* b   = (const float*)d_in[4];      // [2]
    const float* fcw = (const float*)d_in[5];      // [2N]
    const float* fcb = (const float*)d_in[6];      // scalar

    int E  = in_sizes[2];
    int n2 = in_sizes[5];
    int n  = n2 / FOUT;

    const int* rowp = el;
    const int* colp = el + E;

    int headB = (n + 255) / 256;

    // Opt in to >48KB dynamic smem (idempotent; not a stream op, capture-safe).
    cudaFuncSetAttribute(fused_gemm_deg,
                         cudaFuncAttributeMaxDynamicSharedMemorySize, SMEM_TOTAL);

    // 3 dummies keep the fused kernel on the profiler's capture slot (idx 3).
    dummy_kernel<<<1, 32>>>();
    dummy_kernel<<<1, 32>>>();
    dummy_kernel<<<1, 32>>>();
    fused_gemm_deg<<<FUSED_BLOCKS, 256, SMEM_TOTAL>>>(x, W, n, colp, ea, E);
    post_kernel<<<(n + 255) / 256, 256>>>(n);
    edge_kernel<<<(E / 4 + 255) / 256, 256>>>(rowp, colp, ea, E);
    head_kernel<<<headB, 256>>>(b, fcw, fcb, (float*)d_out, n, headB);
}

// round 13
// speedup vs baseline: 1.1628x; 1.1628x over previous
#include <cuda_runtime.h>

// Problem-fixed sizes (reference: N=100000, F_IN=512, F_OUT=2).
#define NMAX 100000
#define FOUT 2
#define FIN 512

// __device__ globals are zero-initialized at module load; every call restores
// them to zero before finishing (post re-zeros g_deg, head resets scalar +
// ticket), so each graph replay sees identical initial state.
__device__ __align__(16) float g_deg[NMAX];
__device__ __align__(16) float g_dis[NMAX];
__device__ __align__(16) float g_h[NMAX * FOUT];   // x @ W
__device__ __align__(16) float g_hs[NMAX * FOUT];  // h * dis (gather source)
__device__ __align__(16) float g_acc[NMAX * FOUT]; // self-loop + edge sums
__device__ float g_acc_scalar;
__device__ unsigned int g_ticket;

// ---------------------------------------------------------------------------
// Dummies align the fused kernel onto the profiler's capture slot (idx 3).
__global__ void dummy_kernel() {}

// ---------------------------------------------------------------------------
// K1 (fused, R4 config — best measured): blocks [0, gemmB) compute h = x @ W
// (one warp per row, 4 independent LDG.128, W staged in smem and read as
// float4); blocks [gemmB, gemmB+degB) do the deg segment-sum atomics and
// overlap with the GEMM's tail waves.
__global__ __launch_bounds__(256) void fused_gemm_deg(
        const float* __restrict__ x, const float* __restrict__ W, int n,
        int gemmB, const int* __restrict__ col, const float* __restrict__ w,
        int E) {
    if ((int)blockIdx.x >= gemmB) {
        // --- deg atomics: 4 edges/thread, vectorized streams ---
        int t = ((int)blockIdx.x - gemmB) * blockDim.x + threadIdx.x;
        int base = t * 4;
        if (base + 3 < E) {
            int4 c4 = *(const int4*)(col + base);
            float4 w4 = *(const float4*)(w + base);
            atomicAdd(&g_deg[c4.x], w4.x);
            atomicAdd(&g_deg[c4.y], w4.y);
            atomicAdd(&g_deg[c4.z], w4.z);
            atomicAdd(&g_deg[c4.w], w4.w);
        } else {
            for (int e = base; e < E; ++e) atomicAdd(&g_deg[col[e]], w[e]);
        }
        return;
    }
    // --- GEMM: one warp per row; 4 independent LDG.128 cover the 2KB row ---
    __shared__ __align__(16) float sW[FIN * FOUT];
    for (int i = threadIdx.x; i < FIN * FOUT; i += blockDim.x) sW[i] = W[i];
    __syncthreads();

    int warp = threadIdx.x >> 5;
    int lane = threadIdx.x & 31;
    int row = (int)blockIdx.x * (blockDim.x >> 5) + warp;
    if (row >= n) return;

    const float4* xr = (const float4*)(x + (size_t)row * FIN);
    const float4* sW4 = (const float4*)sW;

    float4 v0 = __ldg(xr + lane);         // 4 independent loads (MLP 4)
    float4 v1 = __ldg(xr + lane + 32);
    float4 v2 = __ldg(xr + lane + 64);
    float4 v3 = __ldg(xr + lane + 96);

    float a0 = 0.f, a1 = 0.f;
#define ACCUM(v, q)                                                        \
    {                                                                      \
        float4 wa = sW4[2 * (q)];                                          \
        float4 wb = sW4[2 * (q) + 1];                                      \
        a0 += v.x * wa.x + v.y * wa.z + v.z * wb.x + v.w * wb.z;           \
        a1 += v.x * wa.y + v.y * wa.w + v.z * wb.y + v.w * wb.w;           \
    }
    ACCUM(v0, lane)
    ACCUM(v1, lane + 32)
    ACCUM(v2, lane + 64)
    ACCUM(v3, lane + 96)
#undef ACCUM

#pragma unroll
    for (int off = 16; off; off >>= 1) {
        a0 += __shfl_down_sync(0xffffffffu, a0, off);
        a1 += __shfl_down_sync(0xffffffffu, a1, off);
    }
    if (lane == 0) {
        g_h[2 * row + 0] = a0;
        g_h[2 * row + 1] = a1;
    }
}

// ---------------------------------------------------------------------------
// K2: dis = rsqrt(deg + 1); hs = h*dis; acc = hs (self-loop, weight 1);
// re-zero g_deg for the next replay.
__global__ void post_kernel(int n) {
    int i = blockIdx.x * blockDim.x + threadIdx.x;
    if (i >= n) return;
    float d = g_deg[i] + 1.0f;  // self-loop weight
    g_deg[i] = 0.0f;            // restore initial state for next call
    float dis = rsqrtf(d);      // d >= 1 always
    g_dis[i] = dis;
    float2 h = *(const float2*)(g_h + 2 * i);
    float2 hs = make_float2(h.x * dis, h.y * dis);
    *(float2*)(g_hs + 2 * i) = hs;
    *(float2*)(g_acc + 2 * i) = hs;
}

// ---------------------------------------------------------------------------
// K3: edge scatter: acc[col] += hs[row] * w. One random 8B gather + one v2
// RED per edge; 4 edges/thread for gather ILP. (~L2-sector-floor bound.)
__global__ __launch_bounds__(256) void edge_kernel(
        const int* __restrict__ row, const int* __restrict__ col,
        const float* __restrict__ w, int E) {
    int t = blockIdx.x * blockDim.x + threadIdx.x;
    int base = t * 4;
    if (base + 3 < E) {
        int4 r4 = *(const int4*)(row + base);
        int4 c4 = *(const int4*)(col + base);
        float4 w4 = *(const float4*)(w + base);
        float2 h0 = __ldg((const float2*)(g_hs + 2 * r4.x));
        float2 h1 = __ldg((const float2*)(g_hs + 2 * r4.y));
        float2 h2 = __ldg((const float2*)(g_hs + 2 * r4.z));
        float2 h3 = __ldg((const float2*)(g_hs + 2 * r4.w));
        asm volatile("red.global.add.v2.f32 [%0], {%1, %2};" ::
                     "l"(g_acc + 2 * c4.x), "f"(h0.x * w4.x), "f"(h0.y * w4.x) : "memory");
        asm volatile("red.global.add.v2.f32 [%0], {%1, %2};" ::
                     "l"(g_acc + 2 * c4.y), "f"(h1.x * w4.y), "f"(h1.y * w4.y) : "memory");
        asm volatile("red.global.add.v2.f32 [%0], {%1, %2};" ::
                     "l"(g_acc + 2 * c4.z), "f"(h2.x * w4.z), "f"(h2.y * w4.z) : "memory");
        asm volatile("red.global.add.v2.f32 [%0], {%1, %2};" ::
                     "l"(g_acc + 2 * c4.w), "f"(h3.x * w4.w), "f"(h3.y * w4.w) : "memory");
    } else {
        for (int e = base; e < E; ++e) {
            int r = row[e], c = col[e];
            float ww = w[e];
            float2 hv = __ldg((const float2*)(g_hs + 2 * r));
            asm volatile("red.global.add.v2.f32 [%0], {%1, %2};" ::
                         "l"(g_acc + 2 * c), "f"(hv.x * ww), "f"(hv.y * ww) : "memory");
        }
    }
}

// ---------------------------------------------------------------------------
// K4: head (+ fused final): each thread handles ONE float4 = 2 nodes
// (vectorized acc/fcw reads): p = sum relu(dis*acc + b) * fcw. Block-reduce
// into g_acc_scalar; ticketed last block applies sigmoid and resets state.
__global__ __launch_bounds__(512) void head_kernel(
        const float* __restrict__ bvec, const float* __restrict__ fcw,
        const float* __restrict__ fcb, float* __restrict__ out,
        int nq, int nblocks) {          // nq = n2/4 (float4 count)
    int i = blockIdx.x * blockDim.x + threadIdx.x;
    float p = 0.f;
    float b0 = bvec[0], b1 = bvec[1];
    if (i < nq) {
        float4 a4 = *(const float4*)(g_acc + 4 * i);   // nodes 2i, 2i+1
        float4 f4 = __ldg((const float4*)(fcw + 4 * i));
        float2 d2 = *(const float2*)(g_dis + 2 * i);
        p = fmaxf(d2.x * a4.x + b0, 0.f) * f4.x +
            fmaxf(d2.x * a4.y + b1, 0.f) * f4.y +
            fmaxf(d2.y * a4.z + b0, 0.f) * f4.z +
            fmaxf(d2.y * a4.w + b1, 0.f) * f4.w;
    }
#pragma unroll
    for (int off = 16; off; off >>= 1) p += __shfl_down_sync(0xffffffffu, p, off);
    __shared__ float ws[16];
    __shared__ bool is_last;
    int lane = threadIdx.x & 31, wid = threadIdx.x >> 5;
    if (lane == 0) ws[wid] = p;
    __syncthreads();
    if (wid == 0) {
        p = (lane < (blockDim.x >> 5)) ? ws[lane] : 0.f;
#pragma unroll
        for (int off = 8; off; off >>= 1) p += __shfl_down_sync(0xffffffffu, p, off);
        if (lane == 0) {
            atomicAdd(&g_acc_scalar, p);
            __threadfence();
            unsigned int t = atomicAdd(&g_ticket, 1u);
            is_last = (t == (unsigned int)(nblocks - 1));
        }
    }
    __syncthreads();
    if (is_last && threadIdx.x == 0) {
        float l = g_acc_scalar + fcb[0];
        out[0] = 1.f / (1.f + expf(-l));
        g_acc_scalar = 0.0f;   // restore initial state for next call
        g_ticket = 0u;
    }
}

// ---------------------------------------------------------------------------
extern "C" void kernel_launch(void* const* d_in, const int* in_sizes, int n_in,
                              void* d_out, int out_size) {
    const float* x   = (const float*)d_in[0];      // [N, F_IN]
    const int*   el  = (const int*)d_in[1];        // [2, E] int32 (JAX downcast)
    const float* ea  = (const float*)d_in[2];      // [E]
    const float* W   = (const float*)d_in[3];      // [F_IN, 2]
    const float* b   = (const float*)d_in[4];      // [2]
    const float* fcw = (const float*)d_in[5];      // [2N]
    const float* fcb = (const float*)d_in[6];      // scalar

    int E  = in_sizes[2];
    int n2 = in_sizes[5];
    int n  = n2 / FOUT;

    const int* rowp = el;
    const int* colp = el + E;

    int gemmB = (n + 7) / 8;        // 8 warps -> 8 rows per block
    int degB  = (E + 1023) / 1024;  // 256 thr * 4 edges per block
    int nq    = n2 / 4;             // n2 % 4 == 0 (n even)
    int headB = (nq + 511) / 512;

    // 3 dummies keep the fused kernel on the profiler's capture slot (idx 3).
    dummy_kernel<<<1, 32>>>();
    dummy_kernel<<<1, 32>>>();
    dummy_kernel<<<1, 32>>>();
    fused_gemm_deg<<<gemmB + degB, 256>>>(x, W, n, gemmB, colp, ea, E);
    post_kernel<<<(n + 255) / 256, 256>>>(n);
    edge_kernel<<<(E / 4 + 255) / 256, 256>>>(rowp, colp, ea, E);
    head_kernel<<<headB, 512>>>(b, fcw, fcb, (float*)d_out, nq, headB);
}

// round 14
// speedup vs baseline: 1.2378x; 1.0645x over previous
#include <cuda_runtime.h>

// Problem-fixed sizes (reference: N=100000, F_IN=512, F_OUT=2).
#define NMAX 100000
#define FOUT 2
#define FIN 512

// __device__ globals are zero-initialized at module load; every call restores
// them to zero before finishing (post re-zeros g_deg, head resets scalar +
// ticket), so each graph replay sees identical initial state.
__device__ __align__(16) float g_deg[NMAX];
__device__ __align__(16) float g_dis[NMAX];
__device__ __align__(16) float g_h[NMAX * FOUT];   // x @ W
__device__ __align__(16) float g_hs[NMAX * FOUT];  // h * dis (gather source)
__device__ __align__(16) float g_acc[NMAX * FOUT]; // self-loop + edge sums
__device__ float g_acc_scalar;
__device__ unsigned int g_ticket;

// ---------------------------------------------------------------------------
// K1 (fused, best-measured config): blocks [0, gemmB) compute h = x @ W
// (one warp per row, 4 independent LDG.128 with evict-first hint, W staged
// in smem read as float4); blocks [gemmB, gemmB+degB) do the deg segment-sum
// atomics and overlap with the GEMM's tail waves.
__global__ __launch_bounds__(256) void fused_gemm_deg(
        const float* __restrict__ x, const float* __restrict__ W, int n,
        int gemmB, const int* __restrict__ col, const float* __restrict__ w,
        int E) {
    if ((int)blockIdx.x >= gemmB) {
        // --- deg atomics: 4 edges/thread, streaming (evict-first) reads ---
        int t = ((int)blockIdx.x - gemmB) * blockDim.x + threadIdx.x;
        int base = t * 4;
        if (base + 3 < E) {
            int4 c4 = __ldcs((const int4*)(col + base));
            float4 w4 = __ldcs((const float4*)(w + base));
            atomicAdd(&g_deg[c4.x], w4.x);
            atomicAdd(&g_deg[c4.y], w4.y);
            atomicAdd(&g_deg[c4.z], w4.z);
            atomicAdd(&g_deg[c4.w], w4.w);
        } else {
            for (int e = base; e < E; ++e) atomicAdd(&g_deg[col[e]], w[e]);
        }
        return;
    }
    // --- GEMM: one warp per row; 4 independent LDG.128 cover the 2KB row ---
    __shared__ __align__(16) float sW[FIN * FOUT];
    for (int i = threadIdx.x; i < FIN * FOUT; i += blockDim.x) sW[i] = W[i];
    __syncthreads();

    int warp = threadIdx.x >> 5;
    int lane = threadIdx.x & 31;
    int row = (int)blockIdx.x * (blockDim.x >> 5) + warp;
    if (row >= n) return;

    const float4* xr = (const float4*)(x + (size_t)row * FIN);
    const float4* sW4 = (const float4*)sW;

    float4 v0 = __ldcs(xr + lane);        // zero-reuse stream: evict-first
    float4 v1 = __ldcs(xr + lane + 32);
    float4 v2 = __ldcs(xr + lane + 64);
    float4 v3 = __ldcs(xr + lane + 96);

    float a0 = 0.f, a1 = 0.f;
#define ACCUM(v, q)                                                        \
    {                                                                      \
        float4 wa = sW4[2 * (q)];                                          \
        float4 wb = sW4[2 * (q) + 1];                                      \
        a0 += v.x * wa.x + v.y * wa.z + v.z * wb.x + v.w * wb.z;           \
        a1 += v.x * wa.y + v.y * wa.w + v.z * wb.y + v.w * wb.w;           \
    }
    ACCUM(v0, lane)
    ACCUM(v1, lane + 32)
    ACCUM(v2, lane + 64)
    ACCUM(v3, lane + 96)
#undef ACCUM

#pragma unroll
    for (int off = 16; off; off >>= 1) {
        a0 += __shfl_down_sync(0xffffffffu, a0, off);
        a1 += __shfl_down_sync(0xffffffffu, a1, off);
    }
    if (lane == 0) {
        g_h[2 * row + 0] = a0;
        g_h[2 * row + 1] = a1;
    }
}

// ---------------------------------------------------------------------------
// K2: dis = rsqrt(deg + 1); hs = h*dis; acc = hs (self-loop, weight 1);
// re-zero g_deg for the next replay.
__global__ void post_kernel(int n) {
    int i = blockIdx.x * blockDim.x + threadIdx.x;
    if (i >= n) return;
    float d = g_deg[i] + 1.0f;  // self-loop weight
    g_deg[i] = 0.0f;            // restore initial state for next call
    float dis = rsqrtf(d);      // d >= 1 always
    g_dis[i] = dis;
    float2 h = *(const float2*)(g_h + 2 * i);
    float2 hs = make_float2(h.x * dis, h.y * dis);
    *(float2*)(g_hs + 2 * i) = hs;
    *(float2*)(g_acc + 2 * i) = hs;
}

// ---------------------------------------------------------------------------
// K3: edge scatter: acc[col] += hs[row] * w. One random 8B gather + one v2
// RED per edge; 4 edges/thread for gather ILP; edge-list streams use
// evict-first so L2 stays reserved for the hs/acc working sets.
__global__ __launch_bounds__(256) void edge_kernel(
        const int* __restrict__ row, const int* __restrict__ col,
        const float* __restrict__ w, int E) {
    int t = blockIdx.x * blockDim.x + threadIdx.x;
    int base = t * 4;
    if (base + 3 < E) {
        int4 r4 = __ldcs((const int4*)(row + base));
        int4 c4 = __ldcs((const int4*)(col + base));
        float4 w4 = __ldcs((const float4*)(w + base));
        float2 h0 = __ldg((const float2*)(g_hs + 2 * r4.x));
        float2 h1 = __ldg((const float2*)(g_hs + 2 * r4.y));
        float2 h2 = __ldg((const float2*)(g_hs + 2 * r4.z));
        float2 h3 = __ldg((const float2*)(g_hs + 2 * r4.w));
        asm volatile("red.global.add.v2.f32 [%0], {%1, %2};" ::
                     "l"(g_acc + 2 * c4.x), "f"(h0.x * w4.x), "f"(h0.y * w4.x) : "memory");
        asm volatile("red.global.add.v2.f32 [%0], {%1, %2};" ::
                     "l"(g_acc + 2 * c4.y), "f"(h1.x * w4.y), "f"(h1.y * w4.y) : "memory");
        asm volatile("red.global.add.v2.f32 [%0], {%1, %2};" ::
                     "l"(g_acc + 2 * c4.z), "f"(h2.x * w4.z), "f"(h2.y * w4.z) : "memory");
        asm volatile("red.global.add.v2.f32 [%0], {%1, %2};" ::
                     "l"(g_acc + 2 * c4.w), "f"(h3.x * w4.w), "f"(h3.y * w4.w) : "memory");
    } else {
        for (int e = base; e < E; ++e) {
            int r = row[e], c = col[e];
            float ww = w[e];
            float2 hv = __ldg((const float2*)(g_hs + 2 * r));
            asm volatile("red.global.add.v2.f32 [%0], {%1, %2};" ::
                         "l"(g_acc + 2 * c), "f"(hv.x * ww), "f"(hv.y * ww) : "memory");
        }
    }
}

// ---------------------------------------------------------------------------
// K4: head (+ fused final): each thread handles ONE float4 = 2 nodes
// (vectorized acc/fcw reads): p = sum relu(dis*acc + b) * fcw. Block-reduce
// into g_acc_scalar; ticketed last block applies sigmoid and resets state.
__global__ __launch_bounds__(512) void head_kernel(
        const float* __restrict__ bvec, const float* __restrict__ fcw,
        const float* __restrict__ fcb, float* __restrict__ out,
        int nq, int nblocks) {          // nq = n2/4 (float4 count)
    int i = blockIdx.x * blockDim.x + threadIdx.x;
    float p = 0.f;
    float b0 = bvec[0], b1 = bvec[1];
    if (i < nq) {
        float4 a4 = *(const float4*)(g_acc + 4 * i);   // nodes 2i, 2i+1
        float4 f4 = __ldcs((const float4*)(fcw + 4 * i));
        float2 d2 = *(const float2*)(g_dis + 2 * i);
        p = fmaxf(d2.x * a4.x + b0, 0.f) * f4.x +
            fmaxf(d2.x * a4.y + b1, 0.f) * f4.y +
            fmaxf(d2.y * a4.z + b0, 0.f) * f4.z +
            fmaxf(d2.y * a4.w + b1, 0.f) * f4.w;
    }
#pragma unroll
    for (int off = 16; off; off >>= 1) p += __shfl_down_sync(0xffffffffu, p, off);
    __shared__ float ws[16];
    __shared__ bool is_last;
    int lane = threadIdx.x & 31, wid = threadIdx.x >> 5;
    if (lane == 0) ws[wid] = p;
    __syncthreads();
    if (wid == 0) {
        p = (lane < (blockDim.x >> 5)) ? ws[lane] : 0.f;
#pragma unroll
        for (int off = 8; off; off >>= 1) p += __shfl_down_sync(0xffffffffu, p, off);
        if (lane == 0) {
            atomicAdd(&g_acc_scalar, p);
            __threadfence();
            unsigned int t = atomicAdd(&g_ticket, 1u);
            is_last = (t == (unsigned int)(nblocks - 1));
        }
    }
    __syncthreads();
    if (is_last && threadIdx.x == 0) {
        float l = g_acc_scalar + fcb[0];
        out[0] = 1.f / (1.f + expf(-l));
        g_acc_scalar = 0.0f;   // restore initial state for next call
        g_ticket = 0u;
    }
}

// ---------------------------------------------------------------------------
extern "C" void kernel_launch(void* const* d_in, const int* in_sizes, int n_in,
                              void* d_out, int out_size) {
    const float* x   = (const float*)d_in[0];      // [N, F_IN]
    const int*   el  = (const int*)d_in[1];        // [2, E] int32 (JAX downcast)
    const float* ea  = (const float*)d_in[2];      // [E]
    const float* W   = (const float*)d_in[3];      // [F_IN, 2]
    const float* b   = (const float*)d_in[4];      // [2]
    const float* fcw = (const float*)d_in[5];      // [2N]
    const float* fcb = (const float*)d_in[6];      // scalar

    int E  = in_sizes[2];
    int n2 = in_sizes[5];
    int n  = n2 / FOUT;

    const int* rowp = el;
    const int* colp = el + E;

    int gemmB = (n + 7) / 8;        // 8 warps -> 8 rows per block
    int degB  = (E + 1023) / 1024;  // 256 thr * 4 edges per block
    int nq    = n2 / 4;             // n2 % 4 == 0 (n even)
    int headB = (nq + 511) / 512;

    fused_gemm_deg<<<gemmB + degB, 256>>>(x, W, n, gemmB, colp, ea, E);
    post_kernel<<<(n + 255) / 256, 256>>>(n);
    edge_kernel<<<(E / 4 + 255) / 256, 256>>>(rowp, colp, ea, E);
    head_kernel<<<headB, 512>>>(b, fcw, fcb, (float*)d_out, nq, headB);
}